// round 10
// baseline (speedup 1.0000x reference)
#include <cuda_runtime.h>
#include <cuda_bf16.h>
#include <cuda_fp16.h>
#include <cstdint>

#define N_NODES 50000
#define N_EDGES 800000
#define SCAN_BLOCKS ((N_NODES + 255) / 256)   // 196
#define M_TILES (N_NODES / 16)                // 3125, exact

// ---------------- scratch (static __device__, zero-initialized at load) ----------------
__device__ float    g_Q[N_NODES * 128];
// interleaved fp16 K/V: per node 128 words; lane l owns words 4l..4l+3 = {K2l,K2l+1,V2l,V2l+1}
__device__ uint32_t g_KV[N_NODES * 128];
__device__ int      g_row_off[N_NODES + 1];
__device__ int      g_cnt[N_NODES];           // counts -> cursors; re-zeroed by aggregate
__device__ int      g_esrc[N_EDGES];          // src node id per CSR slot
__device__ int      g_part[SCAN_BLOCKS];

// bf16 split of h, packed 4 elems per uint2 (row-major halfword order)
__device__ uint2 g_hhi[N_NODES * 128 / 4];
__device__ uint2 g_hlo[N_NODES * 128 / 4];
// pre-swizzled weight fragments: [z][kstep][ntile][lane] -> {reg0, reg1} of mma B frag
__device__ uint2 g_wfhi[3][8][16][32];
__device__ uint2 g_wflo[3][8][16][32];

__device__ __forceinline__ uint32_t pack_bf2(__nv_bfloat16 a, __nv_bfloat16 b) {
    return (uint32_t)__bfloat16_as_ushort(a) | ((uint32_t)__bfloat16_as_ushort(b) << 16);
}

// ---------------- prep: z=0 split h, z=1 edge count, z=2 weight fragments ----------------
__global__ void __launch_bounds__(256) prep_kernel(
    const float* __restrict__ h, const int* __restrict__ dst,
    const float* __restrict__ Wq, const float* __restrict__ Wk, const float* __restrict__ Wv)
{
    const int z = blockIdx.z;
    const int tid = blockIdx.x * 256 + threadIdx.x;

    if (z == 0) {
        float4 v = *reinterpret_cast<const float4*>(&h[tid * 4]);
        __nv_bfloat16 h0 = __float2bfloat16_rn(v.x);
        __nv_bfloat16 h1 = __float2bfloat16_rn(v.y);
        __nv_bfloat16 h2 = __float2bfloat16_rn(v.z);
        __nv_bfloat16 h3 = __float2bfloat16_rn(v.w);
        uint2 hi, lo;
        hi.x = pack_bf2(h0, h1);
        hi.y = pack_bf2(h2, h3);
        lo.x = pack_bf2(__float2bfloat16_rn(v.x - __bfloat162float(h0)),
                        __float2bfloat16_rn(v.y - __bfloat162float(h1)));
        lo.y = pack_bf2(__float2bfloat16_rn(v.z - __bfloat162float(h2)),
                        __float2bfloat16_rn(v.w - __bfloat162float(h3)));
        g_hhi[tid] = hi;
        g_hlo[tid] = lo;
    } else if (z == 1) {
        if (tid < N_EDGES) atomicAdd(&g_cnt[dst[tid]], 1);
    } else {
        if (tid >= 3 * 8 * 16 * 32) return;
        int lane = tid & 31;
        int nt   = (tid >> 5) & 15;
        int ks   = (tid >> 9) & 7;
        int zz   = tid >> 12;
        const float* W = (zz == 0) ? Wq : (zz == 1) ? Wk : Wv;
        int g = lane >> 2, t = lane & 3;
        int n  = nt * 8 + g;
        int kb = ks * 16 + t * 2;
        float w0 = W[(kb + 0) * 128 + n];
        float w1 = W[(kb + 1) * 128 + n];
        float w2 = W[(kb + 8) * 128 + n];
        float w3 = W[(kb + 9) * 128 + n];
        __nv_bfloat16 b0 = __float2bfloat16_rn(w0);
        __nv_bfloat16 b1 = __float2bfloat16_rn(w1);
        __nv_bfloat16 b2 = __float2bfloat16_rn(w2);
        __nv_bfloat16 b3 = __float2bfloat16_rn(w3);
        uint2 hi, lo;
        hi.x = pack_bf2(b0, b1);
        hi.y = pack_bf2(b2, b3);
        lo.x = pack_bf2(__float2bfloat16_rn(w0 - __bfloat162float(b0)),
                        __float2bfloat16_rn(w1 - __bfloat162float(b1)));
        lo.y = pack_bf2(__float2bfloat16_rn(w2 - __bfloat162float(b2)),
                        __float2bfloat16_rn(w3 - __bfloat162float(b3)));
        g_wfhi[zz][ks][nt][lane] = hi;
        g_wflo[zz][ks][nt][lane] = lo;
    }
}

// ---------------- fused GEMM (one weight per z-block) + scatter (z=3) ----------------
__device__ __forceinline__ void mma_bf16(float& c0, float& c1, float& c2, float& c3,
                                         uint32_t a0, uint32_t a1, uint32_t a2, uint32_t a3,
                                         uint32_t b0, uint32_t b1)
{
    asm volatile(
        "mma.sync.aligned.m16n8k16.row.col.f32.bf16.bf16.f32 "
        "{%0,%1,%2,%3},{%4,%5,%6,%7},{%8,%9},{%0,%1,%2,%3};"
        : "+f"(c0), "+f"(c1), "+f"(c2), "+f"(c3)
        : "r"(a0), "r"(a1), "r"(a2), "r"(a3), "r"(b0), "r"(b1));
}

// grid (3125,1,4): z<3 -> GEMM tile of weight z (16 accums/thread, low regs, high occ)
//                  z==3 -> scatter (latency-bound, hides under gemm waves)
__global__ void __launch_bounds__(128) gemm_scatter(
    const float* __restrict__ bq, const float* __restrict__ bk, const float* __restrict__ bv,
    const int* __restrict__ src, const int* __restrict__ dst)
{
    const int zz = blockIdx.z;
    if (zz == 3) {
        int tid = blockIdx.x * 128 + threadIdx.x;
        #pragma unroll
        for (int r = 0; r < 2; r++) {
            int e = tid + r * (M_TILES * 128);
            int p = atomicAdd(&g_cnt[dst[e]], 1);
            g_esrc[p] = src[e];
        }
        return;
    }

    const int m0   = blockIdx.x * 16;
    const int w    = threadIdx.x >> 5;
    const int lane = threadIdx.x & 31;
    const int g    = lane >> 2;
    const int t    = lane & 3;

    const float* bias = (zz == 0) ? bq : (zz == 1) ? bk : bv;

    float c[4][4];
    #pragma unroll
    for (int nt = 0; nt < 4; nt++) {
        int col = (w * 4 + nt) * 8 + t * 2;
        float b0 = bias[col], b1 = bias[col + 1];
        c[nt][0] = b0; c[nt][1] = b1;
        c[nt][2] = b0; c[nt][3] = b1;
    }

    const uint32_t* Ahi = reinterpret_cast<const uint32_t*>(g_hhi);
    const uint32_t* Alo = reinterpret_cast<const uint32_t*>(g_hlo);
    const int rowA = m0 + g;                 // 64 words per row

    // passes: (Ahi,Bhi), (Ahi,Blo), (Alo,Bhi)
    #pragma unroll
    for (int pass = 0; pass < 3; pass++) {
        const uint32_t* A = (pass == 2) ? Alo : Ahi;
        const bool useLo = (pass == 1);
        #pragma unroll
        for (int ks = 0; ks < 8; ks++) {
            int kw = ks * 8 + t;
            uint32_t a0 = A[rowA * 64 + kw];
            uint32_t a1 = A[(rowA + 8) * 64 + kw];
            uint32_t a2 = A[rowA * 64 + kw + 4];
            uint32_t a3 = A[(rowA + 8) * 64 + kw + 4];
            #pragma unroll
            for (int nt = 0; nt < 4; nt++) {
                uint2 b = useLo ? g_wflo[zz][ks][w * 4 + nt][lane]
                                : g_wfhi[zz][ks][w * 4 + nt][lane];
                mma_bf16(c[nt][0], c[nt][1], c[nt][2], c[nt][3],
                         a0, a1, a2, a3, b.x, b.y);
            }
        }
    }

    if (zz == 0) {
        #pragma unroll
        for (int nt = 0; nt < 4; nt++) {
            int col = (w * 4 + nt) * 8 + t * 2;
            *reinterpret_cast<float2*>(&g_Q[(m0 + g) * 128 + col])     = make_float2(c[nt][0], c[nt][1]);
            *reinterpret_cast<float2*>(&g_Q[(m0 + g + 8) * 128 + col]) = make_float2(c[nt][2], c[nt][3]);
        }
    } else {
        // K (zz=1) -> slot, V (zz=2) -> slot+2 in interleaved g_KV
        const int voff = (zz == 2) ? 2 : 0;
        #pragma unroll
        for (int nt = 0; nt < 4; nt++) {
            int col = (w * 4 + nt) * 8 + t * 2;
            __half2 lo2 = __floats2half2_rn(c[nt][0], c[nt][1]);
            __half2 hi2 = __floats2half2_rn(c[nt][2], c[nt][3]);
            int j = col / 2;
            int slot = (j >> 1) * 4 + (j & 1) + voff;
            g_KV[(m0 + g) * 128 + slot]     = *reinterpret_cast<uint32_t*>(&lo2);
            g_KV[(m0 + g + 8) * 128 + slot] = *reinterpret_cast<uint32_t*>(&hi2);
        }
    }
}

// ---------------- parallel scan, stage 1 ----------------
__global__ void __launch_bounds__(256) scan_part_kernel()
{
    __shared__ int ws[8];
    int gid = blockIdx.x * 256 + threadIdx.x;
    int v = (gid < N_NODES) ? g_cnt[gid] : 0;
    int s = __reduce_add_sync(0xffffffffu, v);
    if ((threadIdx.x & 31) == 0) ws[threadIdx.x >> 5] = s;
    __syncthreads();
    if (threadIdx.x == 0) {
        int tot = 0;
        #pragma unroll
        for (int j = 0; j < 8; j++) tot += ws[j];
        g_part[blockIdx.x] = tot;
    }
}

// ---------------- parallel scan, stage 2 ----------------
__global__ void __launch_bounds__(256) scan_final_kernel()
{
    __shared__ int ps[8];
    __shared__ int ws[8];
    const int t = threadIdx.x, b = blockIdx.x;
    const int lane = t & 31, w = t >> 5;

    int pv = (t < b) ? g_part[t] : 0;
    int psum = __reduce_add_sync(0xffffffffu, pv);
    if (lane == 0) ps[w] = psum;
    __syncthreads();
    int offset = 0;
    #pragma unroll
    for (int j = 0; j < 8; j++) offset += ps[j];

    int gid = b * 256 + t;
    int c = (gid < N_NODES) ? g_cnt[gid] : 0;
    int incl = c;
    #pragma unroll
    for (int d = 1; d < 32; d <<= 1) {
        int u = __shfl_up_sync(0xffffffffu, incl, d);
        if (lane >= d) incl += u;
    }
    if (lane == 31) ws[w] = incl;
    __syncthreads();
    int woff = 0;
    #pragma unroll
    for (int j = 0; j < 8; j++) woff += (j < w) ? ws[j] : 0;

    int excl = offset + woff + incl - c;
    if (gid < N_NODES) {
        g_row_off[gid] = excl;
        g_cnt[gid]     = excl;           // cursor for scatter
    }
    if (gid == N_NODES - 1)
        g_row_off[N_NODES] = excl + c;
}

// ---------------- aggregation: one warp per dst node, 2-edge software pipeline ----------------
// lane l owns columns 4l..4l+3; each 4-lane quad owns one head (D=16).
__global__ void __launch_bounds__(256) aggregate_kernel(float* __restrict__ out)
{
    int warp = (blockIdx.x * blockDim.x + threadIdx.x) >> 5;
    int lane = threadIdx.x & 31;
    if (warp >= N_NODES) return;
    const int node = warp;

    const float4 q = *reinterpret_cast<const float4*>(&g_Q[node * 128 + lane * 4]);
    float4 acc0 = make_float4(0.f, 0.f, 0.f, 0.f);
    float4 acc1 = make_float4(0.f, 0.f, 0.f, 0.f);
    float  zz0 = 0.f, zz1 = 0.f;

    const int beg = g_row_off[node];
    const int end = g_row_off[node + 1];
    int i = beg;

    for (; i + 2 <= end; i += 2) {
        int s0 = g_esrc[i];
        int s1 = g_esrc[i + 1];
        uint4 kv0 = *reinterpret_cast<const uint4*>(&g_KV[s0 * 128 + lane * 4]);
        uint4 kv1 = *reinterpret_cast<const uint4*>(&g_KV[s1 * 128 + lane * 4]);

        float2 k0a = __half22float2(*reinterpret_cast<__half2*>(&kv0.x));
        float2 k0b = __half22float2(*reinterpret_cast<__half2*>(&kv0.y));
        float2 k1a = __half22float2(*reinterpret_cast<__half2*>(&kv1.x));
        float2 k1b = __half22float2(*reinterpret_cast<__half2*>(&kv1.y));

        float p0 = q.x * k0a.x + q.y * k0a.y + q.z * k0b.x + q.w * k0b.y;
        float p1 = q.x * k1a.x + q.y * k1a.y + q.z * k1b.x + q.w * k1b.y;
        p0 += __shfl_xor_sync(0xffffffffu, p0, 1);
        p1 += __shfl_xor_sync(0xffffffffu, p1, 1);
        p0 += __shfl_xor_sync(0xffffffffu, p0, 2);
        p1 += __shfl_xor_sync(0xffffffffu, p1, 2);

        float w0 = __expf(fminf(fmaxf(p0 * 0.25f, -5.f), 5.f));
        float w1 = __expf(fminf(fmaxf(p1 * 0.25f, -5.f), 5.f));

        float2 v0a = __half22float2(*reinterpret_cast<__half2*>(&kv0.z));
        float2 v0b = __half22float2(*reinterpret_cast<__half2*>(&kv0.w));
        float2 v1a = __half22float2(*reinterpret_cast<__half2*>(&kv1.z));
        float2 v1b = __half22float2(*reinterpret_cast<__half2*>(&kv1.w));

        acc0.x += v0a.x * w0;  acc0.y += v0a.y * w0;
        acc0.z += v0b.x * w0;  acc0.w += v0b.y * w0;
        acc1.x += v1a.x * w1;  acc1.y += v1a.y * w1;
        acc1.z += v1b.x * w1;  acc1.w += v1b.y * w1;
        zz0 += w0;
        zz1 += w1;
    }

    if (i < end) {
        int s = g_esrc[i];
        uint4 kv = *reinterpret_cast<const uint4*>(&g_KV[s * 128 + lane * 4]);
        float2 ka = __half22float2(*reinterpret_cast<__half2*>(&kv.x));
        float2 kb = __half22float2(*reinterpret_cast<__half2*>(&kv.y));
        float p = q.x * ka.x + q.y * ka.y + q.z * kb.x + q.w * kb.y;
        p += __shfl_xor_sync(0xffffffffu, p, 1);
        p += __shfl_xor_sync(0xffffffffu, p, 2);
        float wgt = __expf(fminf(fmaxf(p * 0.25f, -5.f), 5.f));
        float2 va = __half22float2(*reinterpret_cast<__half2*>(&kv.z));
        float2 vb = __half22float2(*reinterpret_cast<__half2*>(&kv.w));
        acc0.x += va.x * wgt;  acc0.y += va.y * wgt;
        acc0.z += vb.x * wgt;  acc0.w += vb.y * wgt;
        zz0 += wgt;
    }

    float inv = 1.f / (zz0 + zz1 + 1e-6f);
    float4 o = make_float4((acc0.x + acc1.x) * inv, (acc0.y + acc1.y) * inv,
                           (acc0.z + acc1.z) * inv, (acc0.w + acc1.w) * inv);
    *reinterpret_cast<float4*>(&out[node * 128 + lane * 4]) = o;

    if (lane == 0) g_cnt[node] = 0;                 // restore invariant for next launch
}

// ---------------- launch ----------------
extern "C" void kernel_launch(void* const* d_in, const int* in_sizes, int n_in,
                              void* d_out, int out_size)
{
    const float* h   = (const float*)d_in[0];
    // d_in[1] (e), d_in[8] (We), d_in[9] (be) are unused by the reference output.
    const int*   src = (const int*)d_in[2];
    const int*   dst = (const int*)d_in[3];
    const float* Wq  = (const float*)d_in[4];
    const float* bq  = (const float*)d_in[5];
    const float* Wk  = (const float*)d_in[6];
    const float* bk  = (const float*)d_in[7];
    const float* Wv  = (const float*)d_in[10];
    const float* bv  = (const float*)d_in[11];
    float* out = (float*)d_out;

    dim3 prep_grid(6250, 1, 3);    // z=0: h split, z=1: edge count, z=2: W frags
    prep_kernel<<<prep_grid, 256>>>(h, dst, Wq, Wk, Wv);

    scan_part_kernel<<<SCAN_BLOCKS, 256>>>();
    scan_final_kernel<<<SCAN_BLOCKS, 256>>>();

    dim3 gs_grid(M_TILES, 1, 4);   // z=0..2: gemm per weight, z=3: scatter (hidden)
    gemm_scatter<<<gs_grid, 128>>>(bq, bk, bv, src, dst);

    int agg_blocks = (N_NODES + 7) / 8;   // 8 warps (nodes) per 256-thread block
    aggregate_kernel<<<agg_blocks, 256>>>(out);
}